// round 16
// baseline (speedup 1.0000x reference)
#include <cuda_runtime.h>
#include <cuda_bf16.h>
#include <cuda_fp16.h>
#include <mma.h>
#include <math.h>
#include <stdint.h>

using namespace nvcuda;

#define EMB   768
#define MROWS 1024
#define NN    128
#define KK    128
#define XROWS (3*EMB+2)   // 2306

// ---------------- device scratch ----------------
__device__ __half g_WaH[KK * 2 * EMB];           // fp16 Wa [k][e]
__device__ __nv_bfloat16 g_WcHi[EMB * EMB];
__device__ __nv_bfloat16 g_WcLo[EMB * EMB];
__device__ float g_bc [EMB];
__device__ float g_Pp [(size_t)MROWS * 2 * 2 * EMB];  // [m][pool][nh][e] partial pools
__device__ float g_Ps [(size_t)MROWS * 4];            // [m][pool][nh] partial sums
__device__ __nv_bfloat16 g_PHi[(size_t)MROWS * 3 * EMB];
__device__ __nv_bfloat16 g_PLo[(size_t)MROWS * 3 * EMB];
__device__ float g_Z  [(size_t)MROWS * 3 * EMB];

// ---------------- helpers ----------------
__device__ __forceinline__ uint32_t cvta_smem(const void* p) {
    uint32_t a;
    asm("{ .reg .u64 t; cvta.to.shared.u64 t, %1; cvt.u32.u64 %0, t; }" : "=r"(a) : "l"(p));
    return a;
}
__device__ __forceinline__ float tanh_fast(float x) {
    float y;
    asm("tanh.approx.f32 %0, %1;" : "=f"(y) : "f"(x));
    return y;
}
__device__ __forceinline__ void cp16(uint32_t dst, const void* src) {
    asm volatile("cp.async.cg.shared.global [%0], [%1], 16;" :: "r"(dst), "l"(src) : "memory");
}
__device__ __forceinline__ void cp_commit() {
    asm volatile("cp.async.commit_group;" ::: "memory");
}
__device__ __forceinline__ void cp_wait1() {
    asm volatile("cp.async.wait_group 1;" ::: "memory");
}

// ---------------- 0) Wa -> fp16 ----------------
__global__ void k_split(const float* __restrict__ Wa) {
    int i = blockIdx.x * 256 + threadIdx.x;
    if (i < KK * 2 * EMB) g_WaH[i] = __float2half(Wa[i]);
}

// ---------------- 1) Wc = W2 @ W1, epilogue splits to bf16 hi/lo ---------
__global__ void k_wc(const float* __restrict__ W1, const float* __restrict__ W2) {
    __shared__ float As[64][17];
    __shared__ float Bs[16][65];
    int i0 = blockIdx.y * 64, e0 = blockIdx.x * 64;
    int tx = threadIdx.x & 15, ty = threadIdx.x >> 4;
    float acc[4][4];
#pragma unroll
    for (int i = 0; i < 4; i++)
#pragma unroll
        for (int j = 0; j < 4; j++) acc[i][j] = 0.f;

    for (int t0 = 0; t0 < EMB; t0 += 16) {
        __syncthreads();
        int idx = threadIdx.x;
#pragma unroll
        for (int rep = 0; rep < 4; rep++, idx += 256) {
            int r = idx >> 4, c = idx & 15;
            As[r][c] = W2[(size_t)(i0 + r) * EMB + t0 + c];
        }
        idx = threadIdx.x;
#pragma unroll
        for (int rep = 0; rep < 4; rep++, idx += 256) {
            int r = idx >> 6, c = idx & 63;
            Bs[r][c] = W1[(size_t)(t0 + r) * EMB + e0 + c];
        }
        __syncthreads();
#pragma unroll
        for (int t = 0; t < 16; t++) {
            float a[4], b[4];
#pragma unroll
            for (int u = 0; u < 4; u++) { a[u] = As[ty * 4 + u][t]; b[u] = Bs[t][tx * 4 + u]; }
#pragma unroll
            for (int i = 0; i < 4; i++)
#pragma unroll
                for (int j = 0; j < 4; j++) acc[i][j] += a[i] * b[j];
        }
    }
#pragma unroll
    for (int i = 0; i < 4; i++)
#pragma unroll
        for (int j = 0; j < 4; j++) {
            size_t idx = (size_t)(i0 + ty * 4 + i) * EMB + e0 + tx * 4 + j;
            float v = acc[i][j];
            __nv_bfloat16 h = __float2bfloat16(v);
            g_WcHi[idx] = h;
            g_WcLo[idx] = __float2bfloat16(v - __bfloat162float(h));
        }
}

// ---------------- 1b) bc = W2 @ b1 + b2 (warp per row) ----------------
__global__ void k_bc(const float* __restrict__ W2, const float* __restrict__ b1,
                     const float* __restrict__ b2) {
    int gw = (blockIdx.x * blockDim.x + threadIdx.x) >> 5;
    int lane = threadIdx.x & 31;
    if (gw < EMB) {
        float s = 0.f;
        for (int j = lane; j < EMB; j += 32) s += W2[(size_t)gw * EMB + j] * b1[j];
#pragma unroll
        for (int off = 16; off; off >>= 1)
            s += __shfl_xor_sync(0xffffffffu, s, off);
        if (lane == 0) g_bc[gw] = s + b2[gw];
    }
}

// ---------------- 2) attend: fp16 GEMM + fused unnormalized pooling ------
// smem layout (dynamic, bytes):
//  WRING: 3 stages x [128][72] fp16 (18432B)    = 55296
//  XTILE: 2 bufs x (2 pools x [64][72] fp16)    = 36864  (reused as scr)
#define WRING  0
#define WSTG   18432
#define XTILE  55296
#define XBUF   18432
#define OF_SCR   XTILE            // 8 warps x 320 f
// tail
#define OF_VA    92160    // 128 f
#define OF_SPART 92672    // 256 f
#define OF_BETA  93696    // 128 f (2 pools x 64 n)
#define OF_RED   94208    // 4 f
#define SMEM_DYN 94240

typedef wmma::fragment<wmma::matrix_a, 16, 16, 16, __half, wmma::row_major> FragA;
typedef wmma::fragment<wmma::matrix_b, 16, 16, 16, __half, wmma::row_major> FragB;
typedef wmma::fragment<wmma::accumulator, 16, 16, 16, float> FragC;

// Wa cp.async for chunk cg (full 128 k rows, 64 e); always commits (empty ok)
__device__ __forceinline__ void issue_wa(uint32_t sb32, int cg, int tid) {
    if (cg < 24) {
        bool phA = (cg < 12);
        int e0  = (phA ? cg : cg - 12) * 64;
        int wa0 = phA ? e0 : (EMB + e0);
        uint32_t wbase = sb32 + WRING + (uint32_t)(cg % 3) * WSTG;
#pragma unroll
        for (int r = 0; r < 4; r++) {
            int l = tid + r * 256;              // 1024 x 16B
            int row = l >> 3, c = l & 7;
            cp16(wbase + row * 144 + c * 16,
                 g_WaH + (size_t)row * (2 * EMB) + wa0 + c * 8);
        }
    }
    cp_commit();
}

// LDG fp32 X chunk (this CTA's 64 n-cols) + convert fp16 + STS (buf cg&1)
__device__ __forceinline__ void ldg_cvt_sts(char* sb, int cg, int tid,
                                            const float* __restrict__ Xm, int nh) {
    bool phA = (cg < 12);
    int e0 = (phA ? cg : cg - 12) * 64;
    char* xt = sb + XTILE + (size_t)(cg & 1) * XBUF;
    int np = phA ? 1 : 2;
#pragma unroll 2
    for (int p = 0; p < np; p++) {
        int base = p ? (2 * EMB + 1 + e0) : (phA ? e0 : (EMB + e0));
        char* dh = xt + p * 9216;
#pragma unroll
        for (int r = 0; r < 4; r++) {
            int l = tid + r * 256;              // 1024 float4 per pool (64 rows x 16)
            int row = l >> 4, c4 = l & 15;
            float4 v = __ldg((const float4*)(Xm + (size_t)(base + row) * NN + nh * 64) + c4);
            union { __half2 h[2]; uint2 u; } pk;
            pk.h[0] = __halves2half2(__float2half(v.x), __float2half(v.y));
            pk.h[1] = __halves2half2(__float2half(v.z), __float2half(v.w));
            *(uint2*)(dh + row * 144 + c4 * 8) = pk.u;
        }
    }
}

template <int NP>
__device__ __forceinline__ void mma_chunk(FragC (&acc)[2][2][2], const char* sb,
                                          int cg, int wk, int wn) {
    const __half* wah = (const __half*)(sb + WRING + (size_t)(cg % 3) * WSTG);
    const char* xt = sb + XTILE + (size_t)(cg & 1) * XBUF;
#pragma unroll
    for (int ks = 0; ks < 4; ks++) {
        int ek = ks * 16;
        FragA aH[2];
#pragma unroll
        for (int f = 0; f < 2; f++)
            wmma::load_matrix_sync(aH[f], wah + (wk * 32 + f * 16) * 72 + ek, 72);
#pragma unroll
        for (int p = 0; p < NP; p++) {
            const __half* xh = (const __half*)(xt + p * 9216);
#pragma unroll
            for (int fn = 0; fn < 2; fn++) {
                FragB bH;
                wmma::load_matrix_sync(bH, xh + ek * 72 + wn * 32 + fn * 16, 72);
#pragma unroll
                for (int fk = 0; fk < 2; fk++)
                    wmma::mma_sync(acc[p][fk][fn], aH[fk], bH, acc[p][fk][fn]);
            }
        }
    }
}

__global__ __launch_bounds__(256, 2)
void k_attend(const float* __restrict__ X, const float* __restrict__ va) {
    extern __shared__ __align__(16) char sb[];
    uint32_t sb32 = cvta_smem(sb);

    int m    = blockIdx.x >> 1;
    int nh   = blockIdx.x & 1;                // n-half of this CTA
    int tid  = threadIdx.x;
    int wid  = tid >> 5, lane = tid & 31;
    int wk   = wid & 3, wn = wid >> 2;        // 4 k-groups(32) x 2 n-groups(32)
    const float* Xm = X + (size_t)m * XROWS * NN;

    float* vas   = (float*)(sb + OF_VA);
    float* spart = (float*)(sb + OF_SPART);   // [4 kg][64 n]
    float* betas = (float*)(sb + OF_BETA);    // [2 pools][64 n]
    float* redp  = (float*)(sb + OF_RED);     // [2 pools][2 warps]

    if (tid < 128) vas[tid] = va[tid];

    FragC acc[2][2][2];
#pragma unroll
    for (int fk = 0; fk < 2; fk++)
#pragma unroll
        for (int fn = 0; fn < 2; fn++) wmma::fill_fragment(acc[0][fk][fn], 0.f);

    issue_wa(sb32, 0, tid);
    issue_wa(sb32, 1, tid);

    // ---- 12 hq chunks + 12 dual-pool chunks (64 e each) ----
#pragma unroll 1
    for (int cg = 0; cg < 24; cg++) {
        ldg_cvt_sts(sb, cg, tid, Xm, nh);
        cp_wait1();
        __syncthreads();
        if (cg == 12) {
#pragma unroll
            for (int fk = 0; fk < 2; fk++)
#pragma unroll
                for (int fn = 0; fn < 2; fn++)
#pragma unroll
                    for (int i = 0; i < acc[0][fk][fn].num_elements; i++)
                        acc[1][fk][fn].x[i] = acc[0][fk][fn].x[i];
        }
        issue_wa(sb32, cg + 2, tid);
        if (cg < 12) mma_chunk<1>(acc, sb, cg, wk, wn);
        else         mma_chunk<2>(acc, sb, cg, wk, wn);
    }
    __syncthreads();

    // ---- per pool: scores (full k-sum) -> unnormalized exp -> pooling ----
    float* scr = (float*)(sb + OF_SCR) + wid * 320;   // 16x20 per warp
    int n0 = nh * 64;
#pragma unroll 1
    for (int p = 0; p < 2; p++) {
        const int exp0 = (p == 0) ? EMB : (2 * EMB + 1);
        const int ev   = (p == 0) ? (2 * EMB) : (3 * EMB + 1);

        int j = lane & 15, rh = (lane >> 4) * 8;
#pragma unroll
        for (int fn = 0; fn < 2; fn++) {
            float ps = 0.f;
#pragma unroll
            for (int fk = 0; fk < 2; fk++) {
                wmma::store_matrix_sync(scr, acc[p][fk][fn], 20, wmma::mem_row_major);
                __syncwarp();
#pragma unroll
                for (int r = 0; r < 8; r++) {
                    int kg = wk * 32 + fk * 16 + rh + r;
                    ps += vas[kg] * tanh_fast(scr[(rh + r) * 20 + j]);
                }
                __syncwarp();
            }
            ps += __shfl_xor_sync(0xffffffffu, ps, 16);
            if (lane < 16)
                spart[wk * 64 + wn * 32 + fn * 16 + lane] = ps;
        }
        __syncthreads();

        // beta_n = exp(score_n * valid_n)   (no max-sub: |score| bounded ~20)
        if (tid < 64) {
            float sc = spart[tid] + spart[64 + tid] + spart[128 + tid] + spart[192 + tid];
            float b = expf(sc * Xm[(size_t)ev * NN + n0 + tid]);
            betas[p * 64 + tid] = b;
            float s = b;
#pragma unroll
            for (int off = 16; off; off >>= 1)
                s += __shfl_xor_sync(0xffffffffu, s, off);
            if ((tid & 31) == 0) redp[p * 2 + (tid >> 5)] = s;
        }
        __syncthreads();

        // partial pooling over own 64 n-columns (unnormalized)
        float bb0 = betas[p * 64 + lane], bb1 = betas[p * 64 + 32 + lane];
        float* outp = g_Pp + (((size_t)m * 2 + p) * 2 + nh) * EMB;
#pragma unroll 1
        for (int e = wid; e < EMB; e += 24) {
            const float* r0 = Xm + (size_t)(exp0 + e) * NN + n0;
            const float* r1 = r0 + (size_t)8 * NN;
            const float* r2 = r0 + (size_t)16 * NN;
            float s0 = r0[lane] * bb0 + r0[lane + 32] * bb1;
            float s1 = r1[lane] * bb0 + r1[lane + 32] * bb1;
            float s2 = r2[lane] * bb0 + r2[lane + 32] * bb1;
#pragma unroll
            for (int off = 16; off; off >>= 1) {
                s0 += __shfl_xor_sync(0xffffffffu, s0, off);
                s1 += __shfl_xor_sync(0xffffffffu, s1, off);
                s2 += __shfl_xor_sync(0xffffffffu, s2, off);
            }
            if (lane == 0) {
                outp[e] = s0;
                outp[e + 8] = s1;
                outp[e + 16] = s2;
            }
        }
        __syncthreads();
    }

    if (tid == 0) {
        g_Ps[(size_t)m * 4 + 0 * 2 + nh] = redp[0] + redp[1];
        g_Ps[(size_t)m * 4 + 1 * 2 + nh] = redp[2] + redp[3];
    }
}

// ---------------- 2b) merge partial pools + qv ----------------
__global__ __launch_bounds__(256) void k_merge(const float* __restrict__ X) {
    __shared__ float sums[4];
    int m = blockIdx.x;
    int tid = threadIdx.x;
    const float* Xm = X + (size_t)m * XROWS * NN;

    if (tid < 4) sums[tid] = g_Ps[(size_t)m * 4 + tid];
    __syncthreads();
    float inv0 = 1.f / (sums[0] + sums[1]);
    float inv1 = 1.f / (sums[2] + sums[3]);

    for (int i = tid; i < 2 * EMB; i += 256) {
        int p = i / EMB, ee = i - p * EMB;
        size_t b = ((size_t)m * 2 + p) * 2 * EMB;
        float s = (g_Pp[b + ee] + g_Pp[b + EMB + ee]) * (p ? inv1 : inv0);
        size_t o = ((size_t)m * 3 + p) * EMB + ee;
        __nv_bfloat16 h = __float2bfloat16(s);
        g_PHi[o] = h;
        g_PLo[o] = __float2bfloat16(s - __bfloat162float(h));
    }
    // qv[e] = Xq[e][0]
    for (int e = tid; e < EMB; e += 256) {
        float s = Xm[(size_t)e * NN];
        size_t o = ((size_t)m * 3 + 2) * EMB + e;
        __nv_bfloat16 h = __float2bfloat16(s);
        g_PHi[o] = h;
        g_PLo[o] = __float2bfloat16(s - __bfloat162float(h));
    }
}

// ---------------- 3) MLP: Z = relu(P @ Wc^T + bc), wmma bf16 3-product ----
typedef wmma::fragment<wmma::matrix_a, 16, 16, 16, __nv_bfloat16, wmma::row_major> FragAb;
typedef wmma::fragment<wmma::matrix_b, 16, 16, 16, __nv_bfloat16, wmma::col_major> FragBc;

__global__ __launch_bounds__(256) void k_mlp() {
    __shared__ __nv_bfloat16 Ah[128][48], Al[128][48];
    __shared__ __nv_bfloat16 Bh[128][48], Bl[128][48];
    int r0 = blockIdx.x * 128, i0 = blockIdx.y * 128;
    int tid = threadIdx.x;
    int wid = tid >> 5, lane = tid & 31;
    int wm = wid & 1, wn = wid >> 1;

    FragC acc[4][2];
#pragma unroll
    for (int i = 0; i < 4; i++)
#pragma unroll
        for (int j = 0; j < 2; j++) wmma::fill_fragment(acc[i][j], 0.f);

#pragma unroll 1
    for (int e0 = 0; e0 < EMB; e0 += 32) {
        __syncthreads();
#pragma unroll
        for (int k = 0; k < 4; k++) {
            int l = tid + k * 256;
            int row = l >> 3, c = l & 7;
            *(uint2*)&Ah[row][c * 4] = *((const uint2*)(g_PHi + (size_t)(r0 + row) * EMB + e0) + c);
            *(uint2*)&Al[row][c * 4] = *((const uint2*)(g_PLo + (size_t)(r0 + row) * EMB + e0) + c);
            *(uint2*)&Bh[row][c * 4] = *((const uint2*)(g_WcHi + (size_t)(i0 + row) * EMB + e0) + c);
            *(uint2*)&Bl[row][c * 4] = *((const uint2*)(g_WcLo + (size_t)(i0 + row) * EMB + e0) + c);
        }
        __syncthreads();
#pragma unroll
        for (int ks = 0; ks < 2; ks++) {
            int ek = ks * 16;
            FragBc bh[2], bl[2];
#pragma unroll
            for (int fn = 0; fn < 2; fn++) {
                wmma::load_matrix_sync(bh[fn], &Bh[wn * 32 + fn * 16][ek], 48);
                wmma::load_matrix_sync(bl[fn], &Bl[wn * 32 + fn * 16][ek], 48);
            }
#pragma unroll
            for (int fm = 0; fm < 4; fm++) {
                FragAb ah, al;
                wmma::load_matrix_sync(ah, &Ah[wm * 64 + fm * 16][ek], 48);
                wmma::load_matrix_sync(al, &Al[wm * 64 + fm * 16][ek], 48);
#pragma unroll
                for (int fn = 0; fn < 2; fn++) {
                    wmma::mma_sync(acc[fm][fn], ah, bh[fn], acc[fm][fn]);
                    wmma::mma_sync(acc[fm][fn], ah, bl[fn], acc[fm][fn]);
                    wmma::mma_sync(acc[fm][fn], al, bh[fn], acc[fm][fn]);
                }
            }
        }
    }
    __syncthreads();

    float* scr = (float*)&Ah[0][0] + wid * 320;
#pragma unroll
    for (int fm = 0; fm < 4; fm++)
#pragma unroll
        for (int fn = 0; fn < 2; fn++) {
            wmma::store_matrix_sync(scr, acc[fm][fn], 20, wmma::mem_row_major);
            __syncwarp();
#pragma unroll
            for (int u = 0; u < 8; u++) {
                int el = lane + u * 32;
                int r = el >> 4, c = el & 15;
                int gi = i0 + wn * 32 + fn * 16 + c;
                int gr = r0 + wm * 64 + fm * 16 + r;
                g_Z[(size_t)gr * EMB + gi] = fmaxf(scr[r * 20 + c] + g_bc[gi], 0.f);
            }
            __syncwarp();
        }
}

// ---------------- 4) final head ----------------
__global__ void k_final(const float* __restrict__ W3, const float* __restrict__ b3,
                        float* __restrict__ out) {
    __shared__ float red[8];
    int m = blockIdx.x;
    const float* z1 = g_Z + (size_t)m * 3 * EMB;
    const float* z2 = z1 + EMB;
    const float* zq = z1 + 2 * EMB;
    float s = 0.f;
    for (int i = threadIdx.x; i < EMB; i += 256) {
        float a = z1[i], b = z2[i], q = zq[i];
        s += W3[i] * a + W3[EMB + i] * b +
             W3[2 * EMB + i] * fabsf(a - b) +
             W3[3 * EMB + i] * fabsf(a - q) +
             W3[4 * EMB + i] * fabsf(b - q);
    }
#pragma unroll
    for (int off = 16; off; off >>= 1)
        s += __shfl_xor_sync(0xffffffffu, s, off);
    if ((threadIdx.x & 31) == 0) red[threadIdx.x >> 5] = s;
    __syncthreads();
    if (threadIdx.x == 0) {
        float t = 0.f;
#pragma unroll
        for (int w = 0; w < 8; w++) t += red[w];
        out[m] = fmaxf(t + b3[0], 0.f);
    }
}

// ---------------- launch ----------------
extern "C" void kernel_launch(void* const* d_in, const int* in_sizes, int n_in,
                              void* d_out, int out_size) {
    (void)in_sizes; (void)n_in; (void)out_size;
    const float* X  = (const float*)d_in[0];
    const float* Wa = (const float*)d_in[1];
    const float* va = (const float*)d_in[2];
    const float* W1 = (const float*)d_in[3];
    const float* b1 = (const float*)d_in[4];
    const float* W2 = (const float*)d_in[5];
    const float* b2 = (const float*)d_in[6];
    const float* W3 = (const float*)d_in[7];
    const float* b3 = (const float*)d_in[8];
    float* out = (float*)d_out;

    static int smem_set = 0;
    if (!smem_set) {
        cudaFuncSetAttribute(k_attend, cudaFuncAttributeMaxDynamicSharedMemorySize,
                             SMEM_DYN);
        smem_set = 1;
    }

    k_split<<<768, 256>>>(Wa);
    k_wc<<<dim3(12, 12), 256>>>(W1, W2);
    k_bc<<<96, 256>>>(W2, b1, b2);
    k_attend<<<MROWS * 2, 256, SMEM_DYN>>>(X, va);   // launch #4 -> ncu capture
    k_merge<<<MROWS, 256>>>(X);
    k_mlp<<<dim3(24, 6), 256>>>();
    k_final<<<MROWS, 256>>>(W3, b3, out);
}

// round 17
// speedup vs baseline: 1.2270x; 1.2270x over previous
#include <cuda_runtime.h>
#include <cuda_bf16.h>
#include <cuda_fp16.h>
#include <mma.h>
#include <math.h>
#include <stdint.h>

using namespace nvcuda;

#define EMB   768
#define MROWS 1024
#define NN    128
#define KK    128
#define XROWS (3*EMB+2)   // 2306

// ---------------- device scratch ----------------
__device__ __half g_WaH[KK * 2 * EMB];           // fp16 Wa [k][e]
__device__ __half g_WcH[EMB * EMB];              // fp16 Wc = W2@W1
__device__ float g_bc [EMB];
__device__ float g_Sp [(size_t)MROWS * 2 * NN];  // [m][pool][n] final scores (pre-mask)
__device__ __half g_PH [(size_t)MROWS * 3 * EMB];
__device__ float g_Z  [(size_t)MROWS * 3 * EMB];

// ---------------- helpers ----------------
__device__ __forceinline__ uint32_t cvta_smem(const void* p) {
    uint32_t a;
    asm("{ .reg .u64 t; cvta.to.shared.u64 t, %1; cvt.u32.u64 %0, t; }" : "=r"(a) : "l"(p));
    return a;
}
__device__ __forceinline__ float tanh_fast(float x) {
    float y;
    asm("tanh.approx.f32 %0, %1;" : "=f"(y) : "f"(x));
    return y;
}
__device__ __forceinline__ void cp16(uint32_t dst, const void* src) {
    asm volatile("cp.async.cg.shared.global [%0], [%1], 16;" :: "r"(dst), "l"(src) : "memory");
}
__device__ __forceinline__ void cp_commit() {
    asm volatile("cp.async.commit_group;" ::: "memory");
}
__device__ __forceinline__ void cp_wait1() {
    asm volatile("cp.async.wait_group 1;" ::: "memory");
}

// ---------------- 0) Wa -> fp16 ----------------
__global__ void k_split(const float* __restrict__ Wa) {
    int i = blockIdx.x * 256 + threadIdx.x;
    if (i < KK * 2 * EMB) g_WaH[i] = __float2half(Wa[i]);
}

// ---------------- 1) Wc = W2 @ W1 (epilogue -> fp16) ----------------
__global__ void k_wc(const float* __restrict__ W1, const float* __restrict__ W2) {
    __shared__ float As[64][17];
    __shared__ float Bs[16][65];
    int i0 = blockIdx.y * 64, e0 = blockIdx.x * 64;
    int tx = threadIdx.x & 15, ty = threadIdx.x >> 4;
    float acc[4][4];
#pragma unroll
    for (int i = 0; i < 4; i++)
#pragma unroll
        for (int j = 0; j < 4; j++) acc[i][j] = 0.f;

    for (int t0 = 0; t0 < EMB; t0 += 16) {
        __syncthreads();
        int idx = threadIdx.x;
#pragma unroll
        for (int rep = 0; rep < 4; rep++, idx += 256) {
            int r = idx >> 4, c = idx & 15;
            As[r][c] = W2[(size_t)(i0 + r) * EMB + t0 + c];
        }
        idx = threadIdx.x;
#pragma unroll
        for (int rep = 0; rep < 4; rep++, idx += 256) {
            int r = idx >> 6, c = idx & 63;
            Bs[r][c] = W1[(size_t)(t0 + r) * EMB + e0 + c];
        }
        __syncthreads();
#pragma unroll
        for (int t = 0; t < 16; t++) {
            float a[4], b[4];
#pragma unroll
            for (int u = 0; u < 4; u++) { a[u] = As[ty * 4 + u][t]; b[u] = Bs[t][tx * 4 + u]; }
#pragma unroll
            for (int i = 0; i < 4; i++)
#pragma unroll
                for (int j = 0; j < 4; j++) acc[i][j] += a[i] * b[j];
        }
    }
#pragma unroll
    for (int i = 0; i < 4; i++)
#pragma unroll
        for (int j = 0; j < 4; j++)
            g_WcH[(size_t)(i0 + ty * 4 + i) * EMB + e0 + tx * 4 + j] = __float2half(acc[i][j]);
}

// ---------------- 1b) bc = W2 @ b1 + b2 (warp per row) ----------------
__global__ void k_bc(const float* __restrict__ W2, const float* __restrict__ b1,
                     const float* __restrict__ b2) {
    int gw = (blockIdx.x * blockDim.x + threadIdx.x) >> 5;
    int lane = threadIdx.x & 31;
    if (gw < EMB) {
        float s = 0.f;
        for (int j = lane; j < EMB; j += 32) s += W2[(size_t)gw * EMB + j] * b1[j];
#pragma unroll
        for (int off = 16; off; off >>= 1)
            s += __shfl_xor_sync(0xffffffffu, s, off);
        if (lane == 0) g_bc[gw] = s + b2[gw];
    }
}

// ---------------- 2) attend GEMM: fp16, 2 CTAs per m (n-split) ----------
// smem layout (dynamic, bytes):
//  WRING: 3 stages x [128][72] fp16 (18432B)    = 55296
//  XTILE: 2 bufs x (2 pools x [64][72] fp16)    = 36864
#define WRING  0
#define WSTG   18432
#define XTILE  55296
#define XBUF   18432
#define OF_VA    92160    // 128 f
#define OF_SPART 92672    // 256 f
#define SMEM_DYN 93696

typedef wmma::fragment<wmma::matrix_a, 16, 16, 16, __half, wmma::row_major> FragA;
typedef wmma::fragment<wmma::matrix_b, 16, 16, 16, __half, wmma::row_major> FragB;
typedef wmma::fragment<wmma::matrix_b, 16, 16, 16, __half, wmma::col_major> FragBc;
typedef wmma::fragment<wmma::accumulator, 16, 16, 16, float> FragC;

// Wa cp.async for chunk cg (full 128 k rows, 64 e); always commits (empty ok)
__device__ __forceinline__ void issue_wa(uint32_t sb32, int cg, int tid) {
    if (cg < 24) {
        bool phA = (cg < 12);
        int e0  = (phA ? cg : cg - 12) * 64;
        int wa0 = phA ? e0 : (EMB + e0);
        uint32_t wbase = sb32 + WRING + (uint32_t)(cg % 3) * WSTG;
#pragma unroll
        for (int r = 0; r < 4; r++) {
            int l = tid + r * 256;              // 1024 x 16B
            int row = l >> 3, c = l & 7;
            cp16(wbase + row * 144 + c * 16,
                 g_WaH + (size_t)row * (2 * EMB) + wa0 + c * 8);
        }
    }
    cp_commit();
}

// LDG fp32 X chunk (this CTA's 64 n-cols) + convert fp16 + STS (buf cg&1)
__device__ __forceinline__ void ldg_cvt_sts(char* sb, int cg, int tid,
                                            const float* __restrict__ Xm, int nh) {
    bool phA = (cg < 12);
    int e0 = (phA ? cg : cg - 12) * 64;
    char* xt = sb + XTILE + (size_t)(cg & 1) * XBUF;
    int np = phA ? 1 : 2;
#pragma unroll 2
    for (int p = 0; p < np; p++) {
        int base = p ? (2 * EMB + 1 + e0) : (phA ? e0 : (EMB + e0));
        char* dh = xt + p * 9216;
#pragma unroll
        for (int r = 0; r < 4; r++) {
            int l = tid + r * 256;              // 1024 float4 per pool (64 rows x 16)
            int row = l >> 4, c4 = l & 15;
            float4 v = __ldg((const float4*)(Xm + (size_t)(base + row) * NN + nh * 64) + c4);
            union { __half2 h[2]; uint2 u; } pk;
            pk.h[0] = __halves2half2(__float2half(v.x), __float2half(v.y));
            pk.h[1] = __halves2half2(__float2half(v.z), __float2half(v.w));
            *(uint2*)(dh + row * 144 + c4 * 8) = pk.u;
        }
    }
}

template <int NP>
__device__ __forceinline__ void mma_chunk(FragC (&acc)[2][2][2], const char* sb,
                                          int cg, int wk, int wn) {
    const __half* wah = (const __half*)(sb + WRING + (size_t)(cg % 3) * WSTG);
    const char* xt = sb + XTILE + (size_t)(cg & 1) * XBUF;
#pragma unroll
    for (int ks = 0; ks < 4; ks++) {
        int ek = ks * 16;
        FragA aH[2];
#pragma unroll
        for (int f = 0; f < 2; f++)
            wmma::load_matrix_sync(aH[f], wah + (wk * 32 + f * 16) * 72 + ek, 72);
#pragma unroll
        for (int p = 0; p < NP; p++) {
            const __half* xh = (const __half*)(xt + p * 9216);
#pragma unroll
            for (int fn = 0; fn < 2; fn++) {
                FragB bH;
                wmma::load_matrix_sync(bH, xh + ek * 72 + wn * 32 + fn * 16, 72);
#pragma unroll
                for (int fk = 0; fk < 2; fk++)
                    wmma::mma_sync(acc[p][fk][fn], aH[fk], bH, acc[p][fk][fn]);
            }
        }
    }
}

__global__ __launch_bounds__(256, 2)
void k_attend(const float* __restrict__ X, const float* __restrict__ va) {
    extern __shared__ __align__(16) char sb[];
    uint32_t sb32 = cvta_smem(sb);

    int m    = blockIdx.x >> 1;
    int nh   = blockIdx.x & 1;                // n-half of this CTA
    int tid  = threadIdx.x;
    int wid  = tid >> 5, lane = tid & 31;
    int wk   = wid & 3, wn = wid >> 2;        // 4 k-groups(32) x 2 n-groups(32)
    const float* Xm = X + (size_t)m * XROWS * NN;

    float* vas   = (float*)(sb + OF_VA);
    float* spart = (float*)(sb + OF_SPART);   // [4 kg][64 n]

    if (tid < 128) vas[tid] = va[tid];

    FragC acc[2][2][2];
#pragma unroll
    for (int fk = 0; fk < 2; fk++)
#pragma unroll
        for (int fn = 0; fn < 2; fn++) wmma::fill_fragment(acc[0][fk][fn], 0.f);

    issue_wa(sb32, 0, tid);
    issue_wa(sb32, 1, tid);

    // ---- 12 hq chunks + 12 dual-pool chunks (64 e each) ----
#pragma unroll 1
    for (int cg = 0; cg < 24; cg++) {
        ldg_cvt_sts(sb, cg, tid, Xm, nh);
        cp_wait1();
        __syncthreads();
        if (cg == 12) {
#pragma unroll
            for (int fk = 0; fk < 2; fk++)
#pragma unroll
                for (int fn = 0; fn < 2; fn++)
#pragma unroll
                    for (int i = 0; i < acc[0][fk][fn].num_elements; i++)
                        acc[1][fk][fn].x[i] = acc[0][fk][fn].x[i];
        }
        issue_wa(sb32, cg + 2, tid);
        if (cg < 12) mma_chunk<1>(acc, sb, cg, wk, wn);
        else         mma_chunk<2>(acc, sb, cg, wk, wn);
    }
    __syncthreads();

    // ---- scores: full k-sum within CTA, for this CTA's 64 n ----
    float* scr = (float*)(sb + XTILE) + wid * 320;   // 16x20 per warp
#pragma unroll 1
    for (int p = 0; p < 2; p++) {
        int j = lane & 15, rh = (lane >> 4) * 8;
#pragma unroll
        for (int fn = 0; fn < 2; fn++) {
            float ps = 0.f;
#pragma unroll
            for (int fk = 0; fk < 2; fk++) {
                wmma::store_matrix_sync(scr, acc[p][fk][fn], 20, wmma::mem_row_major);
                __syncwarp();
#pragma unroll
                for (int r = 0; r < 8; r++) {
                    int kg = wk * 32 + fk * 16 + rh + r;
                    ps += vas[kg] * tanh_fast(scr[(rh + r) * 20 + j]);
                }
                __syncwarp();
            }
            ps += __shfl_xor_sync(0xffffffffu, ps, 16);
            if (lane < 16)
                spart[wk * 64 + wn * 32 + fn * 16 + lane] = ps;
        }
        __syncthreads();
        if (tid < 64)
            g_Sp[((size_t)m * 2 + p) * NN + nh * 64 + tid] =
                spart[tid] + spart[64 + tid] + spart[128 + tid] + spart[192 + tid];
        __syncthreads();
    }
}

// ---------------- 2b) pool: softmax + weighted sum + qv (CTA per m,pool) --
__global__ __launch_bounds__(256) void k_pool(const float* __restrict__ X) {
    __shared__ float scs[128], beta[128], red[1];
    int m = blockIdx.x;
    int p = blockIdx.y;
    int tid = threadIdx.x;
    int wid = tid >> 5, lane = tid & 31;
    const float* Xm = X + (size_t)m * XROWS * NN;

    const int exp0 = (p == 0) ? EMB : (2 * EMB + 1);
    const int ev   = (p == 0) ? (2 * EMB) : (3 * EMB + 1);

    if (tid < 128)
        scs[tid] = g_Sp[((size_t)m * 2 + p) * NN + tid] * Xm[(size_t)ev * NN + tid];
    __syncthreads();
    if (tid < 32) {
        float mx = fmaxf(fmaxf(scs[tid], scs[tid + 32]),
                         fmaxf(scs[tid + 64], scs[tid + 96]));
#pragma unroll
        for (int off = 16; off; off >>= 1)
            mx = fmaxf(mx, __shfl_xor_sync(0xffffffffu, mx, off));
        if (tid == 0) red[0] = mx;
    }
    __syncthreads();
    float mx = red[0];
    if (tid < 128) beta[tid] = expf(scs[tid] - mx);
    __syncthreads();
    if (tid < 32) {
        float s = beta[tid] + beta[tid + 32] + beta[tid + 64] + beta[tid + 96];
#pragma unroll
        for (int off = 16; off; off >>= 1)
            s += __shfl_xor_sync(0xffffffffu, s, off);
        if (tid == 0) red[0] = s;
    }
    __syncthreads();
    float inv = 1.f / red[0];
    if (tid < 128) beta[tid] *= inv;
    __syncthreads();

    float b0 = beta[lane], b1v = beta[lane + 32], b2v = beta[lane + 64], b3v = beta[lane + 96];
#pragma unroll 1
    for (int e = wid; e < EMB; e += 24) {
        const float* r0 = Xm + (size_t)(exp0 + e) * NN;
        const float* r1 = r0 + (size_t)8 * NN;
        const float* r2 = r0 + (size_t)16 * NN;
        float s0 = r0[lane] * b0 + r0[lane + 32] * b1v + r0[lane + 64] * b2v + r0[lane + 96] * b3v;
        float s1 = r1[lane] * b0 + r1[lane + 32] * b1v + r1[lane + 64] * b2v + r1[lane + 96] * b3v;
        float s2 = r2[lane] * b0 + r2[lane + 32] * b1v + r2[lane + 64] * b2v + r2[lane + 96] * b3v;
#pragma unroll
        for (int off = 16; off; off >>= 1) {
            s0 += __shfl_xor_sync(0xffffffffu, s0, off);
            s1 += __shfl_xor_sync(0xffffffffu, s1, off);
            s2 += __shfl_xor_sync(0xffffffffu, s2, off);
        }
        if (lane == 0) {
            size_t o = ((size_t)m * 3 + p) * EMB + e;
            g_PH[o]      = __float2half(s0);
            g_PH[o + 8]  = __float2half(s1);
            g_PH[o + 16] = __float2half(s2);
        }
    }

    // qv[e] = Xq[e][0]  (pool-0 CTA only)
    if (p == 0) {
        for (int e = tid; e < EMB; e += 256)
            g_PH[((size_t)m * 3 + 2) * EMB + e] = __float2half(Xm[(size_t)e * NN]);
    }
}

// ---------------- 3) MLP: Z = relu(P @ Wc^T + bc), fp16 single-product ---
__global__ __launch_bounds__(256) void k_mlp() {
    __shared__ __half Ah[128][40];   // stride 80B: 16B-aligned, conflict-free ldsm
    __shared__ __half Bh[128][40];
    int r0 = blockIdx.x * 128, i0 = blockIdx.y * 128;
    int tid = threadIdx.x;
    int wid = tid >> 5, lane = tid & 31;
    int wm = wid & 1, wn = wid >> 1;   // 2 m-groups(64) x 4 n-groups(32)

    FragC acc[4][2];
#pragma unroll
    for (int i = 0; i < 4; i++)
#pragma unroll
        for (int j = 0; j < 2; j++) wmma::fill_fragment(acc[i][j], 0.f);

#pragma unroll 1
    for (int e0 = 0; e0 < EMB; e0 += 32) {
        __syncthreads();
#pragma unroll
        for (int k = 0; k < 4; k++) {
            int l = tid + k * 256;      // 1024 uint2 per tile (128 rows x 8)
            int row = l >> 3, c = l & 7;
            *(uint2*)&Ah[row][c * 4] = *((const uint2*)(g_PH + (size_t)(r0 + row) * EMB + e0) + c);
            *(uint2*)&Bh[row][c * 4] = *((const uint2*)(g_WcH + (size_t)(i0 + row) * EMB + e0) + c);
        }
        __syncthreads();
#pragma unroll
        for (int ks = 0; ks < 2; ks++) {
            int ek = ks * 16;
            FragBc bh[2];
#pragma unroll
            for (int fn = 0; fn < 2; fn++)
                wmma::load_matrix_sync(bh[fn], &Bh[wn * 32 + fn * 16][ek], 40);
#pragma unroll
            for (int fm = 0; fm < 4; fm++) {
                FragA ah;
                wmma::load_matrix_sync(ah, &Ah[wm * 64 + fm * 16][ek], 40);
#pragma unroll
                for (int fn = 0; fn < 2; fn++)
                    wmma::mma_sync(acc[fm][fn], ah, bh[fn], acc[fm][fn]);
            }
        }
    }
    __syncthreads();

    float* scr = (float*)&Ah[0][0] + wid * 320;   // 8 warps x 320f = 10240B = |Ah|
#pragma unroll
    for (int fm = 0; fm < 4; fm++)
#pragma unroll
        for (int fn = 0; fn < 2; fn++) {
            wmma::store_matrix_sync(scr, acc[fm][fn], 20, wmma::mem_row_major);
            __syncwarp();
#pragma unroll
            for (int u = 0; u < 8; u++) {
                int el = lane + u * 32;
                int r = el >> 4, c = el & 15;
                int gi = i0 + wn * 32 + fn * 16 + c;
                int gr = r0 + wm * 64 + fm * 16 + r;
                g_Z[(size_t)gr * EMB + gi] = fmaxf(scr[r * 20 + c] + g_bc[gi], 0.f);
            }
            __syncwarp();
        }
}

// ---------------- 4) final head ----------------
__global__ void k_final(const float* __restrict__ W3, const float* __restrict__ b3,
                        float* __restrict__ out) {
    __shared__ float red[8];
    int m = blockIdx.x;
    const float* z1 = g_Z + (size_t)m * 3 * EMB;
    const float* z2 = z1 + EMB;
    const float* zq = z1 + 2 * EMB;
    float s = 0.f;
    for (int i = threadIdx.x; i < EMB; i += 256) {
        float a = z1[i], b = z2[i], q = zq[i];
        s += W3[i] * a + W3[EMB + i] * b +
             W3[2 * EMB + i] * fabsf(a - b) +
             W3[3 * EMB + i] * fabsf(a - q) +
             W3[4 * EMB + i] * fabsf(b - q);
    }
#pragma unroll
    for (int off = 16; off; off >>= 1)
        s += __shfl_xor_sync(0xffffffffu, s, off);
    if ((threadIdx.x & 31) == 0) red[threadIdx.x >> 5] = s;
    __syncthreads();
    if (threadIdx.x == 0) {
        float t = 0.f;
#pragma unroll
        for (int w = 0; w < 8; w++) t += red[w];
        out[m] = fmaxf(t + b3[0], 0.f);
    }
}

// ---------------- launch ----------------
extern "C" void kernel_launch(void* const* d_in, const int* in_sizes, int n_in,
                              void* d_out, int out_size) {
    (void)in_sizes; (void)n_in; (void)out_size;
    const float* X  = (const float*)d_in[0];
    const float* Wa = (const float*)d_in[1];
    const float* va = (const float*)d_in[2];
    const float* W1 = (const float*)d_in[3];
    const float* b1 = (const float*)d_in[4];
    const float* W2 = (const float*)d_in[5];
    const float* b2 = (const float*)d_in[6];
    const float* W3 = (const float*)d_in[7];
    const float* b3 = (const float*)d_in[8];
    float* out = (float*)d_out;

    static int smem_set = 0;
    if (!smem_set) {
        cudaFuncSetAttribute(k_attend, cudaFuncAttributeMaxDynamicSharedMemorySize,
                             SMEM_DYN);
        smem_set = 1;
    }

    k_split<<<768, 256>>>(Wa);
    k_wc<<<dim3(12, 12), 256>>>(W1, W2);
    k_bc<<<96, 256>>>(W2, b1, b2);
    k_attend<<<MROWS * 2, 256, SMEM_DYN>>>(X, va);   // launch #4 -> ncu capture
    k_pool<<<dim3(MROWS, 2), 256>>>(X);
    k_mlp<<<dim3(24, 6), 256>>>();
    k_final<<<MROWS, 256>>>(W3, b3, out);
}